// round 15
// baseline (speedup 1.0000x reference)
#include <cuda_runtime.h>
#include <cuda_bf16.h>
#include <cstdint>

#define NN 50000
#define EE 600000
#define DD 128
#define KK 8
#define BB 64
#define ED 16
#define PS 8     // slices per graph for pooling
#define PADW 132 // padded row stride (floats) for conflict-free mma frag loads
#define EASTR 20 // sEA row stride (floats), conflict-free a-frag loads
#define RSTR 136 // sEMB row stride (floats): 2-way-max STS, conflict-free LDS.128

// Scratch (device globals; no runtime alloc)
__device__ float g_h[NN * DD];            // (1+eps)*x + agg
__device__ float g_xres[NN * DD];         // MLP output
__device__ float g_psum[BB * KK * DD];    // pocket sums
__device__ float g_pcnt[BB * KK];         // pocket counts
__device__ float g_pemb[BB * KK * DD];    // pocket embeddings
__device__ int   g_gstart[BB + 1];        // graph start offsets (batch sorted)
__device__ float g_part[BB * PS * KK * DD];   // pooling partials (atomic-free)
__device__ float g_cntpart[BB * PS * KK];
// Pre-converted W1/W2, fragment-major tf32 hi/lo ([w][ktile16][ntile16][lane32][slot2])
__device__ uint32_t g_Wph[2 * 16384];
__device__ uint32_t g_Wpl[2 * 16384];
// Pre-converted We (16x128): 2 ktiles x 16 ntiles, same frag layout
__device__ uint32_t g_Weh[2048];
__device__ uint32_t g_Wel[2048];

// tf32 helpers
__device__ __forceinline__ uint32_t tf32_hi(float f) {
    uint32_t u;
    asm("cvt.rna.tf32.f32 %0, %1;" : "=r"(u) : "f"(f));
    return u;
}
#define MMA_TF32(d, a0, a1, a2, a3, b0, b1) \
    asm volatile("mma.sync.aligned.m16n8k8.row.col.f32.tf32.tf32.f32 " \
                 "{%0,%1,%2,%3}, {%4,%5,%6,%7}, {%8,%9}, {%0,%1,%2,%3};" \
                 : "+f"(d[0]), "+f"(d[1]), "+f"(d[2]), "+f"(d[3]) \
                 : "r"(a0), "r"(a1), "r"(a2), "r"(a3), "r"(b0), "r"(b1))

// ---------------------------------------------------------------------------
// Kernel 0: g_h = (1+eps)*x
// ---------------------------------------------------------------------------
__global__ void init_kernel(const float* __restrict__ x, const float* __restrict__ epsp) {
    const float c = 1.0f + epsp[0];
    int tid = blockIdx.x * blockDim.x + threadIdx.x;
    int stride = gridDim.x * blockDim.x;
    const float4* x4 = (const float4*)x;
    float4* h4 = (float4*)g_h;
    for (int i = tid; i < NN * DD / 4; i += stride) {
        float4 v = x4[i];
        v.x *= c; v.y *= c; v.z *= c; v.w *= c;
        h4[i] = v;
    }
}

// ---------------------------------------------------------------------------
// Kernel 0b: graph boundary offsets from sorted batch
// ---------------------------------------------------------------------------
__global__ void bounds_kernel(const int* __restrict__ batch) {
    int n = blockIdx.x * blockDim.x + threadIdx.x;
    if (n >= NN) return;
    int b1 = batch[n];
    int b0 = (n == 0) ? -1 : batch[n - 1];
    for (int g = b0 + 1; g <= b1; g++) g_gstart[g] = n;
    if (n == NN - 1)
        for (int g = b1 + 1; g <= BB; g++) g_gstart[g] = NN;
}

// ---------------------------------------------------------------------------
// Kernel 0c: convert W1/W2 to fragment-major tf32 hi/lo (layout verified R12+)
// ---------------------------------------------------------------------------
__global__ void wconv_kernel(const float* __restrict__ W1, const float* __restrict__ W2) {
    int idx = blockIdx.x * blockDim.x + threadIdx.x;   // over 2*16*16*32
    if (idx >= 2 * 16 * 16 * 32) return;
    int w = idx >> 13;
    int rest = idx & 8191;
    int tk = rest >> 9;
    int tn = (rest >> 5) & 15;
    int lane = rest & 31;
    int tq = lane >> 2, tr = lane & 3;
    const float* W = (w == 0) ? W1 : W2;
    float v0 = W[(tk * 8 + tr) * DD + tn * 8 + tq];
    float v1 = W[(tk * 8 + tr + 4) * DD + tn * 8 + tq];
    int base = w * 16384 + (tk * 16 + tn) * 64 + lane * 2;
    uint32_t h0 = tf32_hi(v0), h1 = tf32_hi(v1);
    g_Wph[base]     = h0;
    g_Wph[base + 1] = h1;
    g_Wpl[base]     = tf32_hi(v0 - __uint_as_float(h0));
    g_Wpl[base + 1] = tf32_hi(v1 - __uint_as_float(h1));
}

// ---------------------------------------------------------------------------
// Kernel 0d: convert We (16x128) to fragment-major tf32 hi/lo (2 kt, 16 nt)
// ---------------------------------------------------------------------------
__global__ void econv_kernel(const float* __restrict__ We) {
    int idx = blockIdx.x * blockDim.x + threadIdx.x;   // over 2*16*32
    if (idx >= 2 * 16 * 32) return;
    int kt = idx >> 9;
    int nt = (idx >> 5) & 15;
    int lane = idx & 31;
    int tq = lane >> 2, tr = lane & 3;
    float v0 = We[(kt * 8 + tr) * DD + nt * 8 + tq];
    float v1 = We[(kt * 8 + tr + 4) * DD + nt * 8 + tq];
    int base = (kt * 16 + nt) * 64 + lane * 2;
    uint32_t h0 = tf32_hi(v0), h1 = tf32_hi(v1);
    g_Weh[base]     = h0;
    g_Weh[base + 1] = h1;
    g_Wel[base]     = tf32_hi(v0 - __uint_as_float(h0));
    g_Wel[base + 1] = tf32_hi(v1 - __uint_as_float(h1));
}

// ---------------------------------------------------------------------------
// Kernel 1: edges on TENSOR CORES. Per 64-edge iteration:
//   A: stage ea[64][16] into sEA (coalesced).
//   B: warp-pair p computes emb[16 edges][128] via m16n8k8 3xTF32
//      (warp half h owns 64 cols); store row-major to sEMB.
//   C: each warp epilogues 8 edges: relu(x[src]+emb+be) -> red.v4 g_h[dst].
// ---------------------------------------------------------------------------
__global__ void __launch_bounds__(256)
edge_kernel(const float* __restrict__ x,
            const int* __restrict__ ei,
            const float* __restrict__ ea,
            const float* __restrict__ be) {
    __shared__ float sEA[64 * EASTR];    // 5.0 KB
    __shared__ float sEMB[64 * RSTR];    // 34.8 KB
    const int tid = threadIdx.x;
    const int lane = tid & 31, warp = tid >> 5;
    const int tq = lane >> 2, tr = lane & 3;
    const int p = warp >> 1, h = warp & 1;
    const int* __restrict__ srcp = ei;
    const int* __restrict__ dstp = ei + EE;
    const float4 bbv = *(const float4*)(be + lane * 4);

    for (int e0 = blockIdx.x * 64; e0 < EE; e0 += gridDim.x * 64) {
        // ---- Phase A: stage ea tile ----
        {
            int r = tid >> 2, c = (tid & 3) * 4;
            float4 v = __ldg((const float4*)(ea + (size_t)(e0 + r) * ED + c));
            *(float4*)(sEA + r * EASTR + c) = v;
        }
        __syncthreads();

        // ---- Phase B: mma ----
        float acc[8][4];
#pragma unroll
        for (int nt = 0; nt < 8; nt++)
#pragma unroll
            for (int v = 0; v < 4; v++) acc[nt][v] = 0.f;

        uint32_t ah[2][4], al[2][4];
        {
            const float* b0p = sEA + (p * 16 + tq) * EASTR;
            const float* b8p = sEA + (p * 16 + tq + 8) * EASTR;
#pragma unroll
            for (int ks = 0; ks < 2; ks++) {
                int k0 = ks * 8;
                float f0 = b0p[k0 + tr];
                float f1 = b8p[k0 + tr];
                float f2 = b0p[k0 + tr + 4];
                float f3 = b8p[k0 + tr + 4];
                ah[ks][0] = tf32_hi(f0); ah[ks][1] = tf32_hi(f1);
                ah[ks][2] = tf32_hi(f2); ah[ks][3] = tf32_hi(f3);
                al[ks][0] = __float_as_uint(f0 - __uint_as_float(ah[ks][0]));
                al[ks][1] = __float_as_uint(f1 - __uint_as_float(ah[ks][1]));
                al[ks][2] = __float_as_uint(f2 - __uint_as_float(ah[ks][2]));
                al[ks][3] = __float_as_uint(f3 - __uint_as_float(ah[ks][3]));
            }
        }
#pragma unroll
        for (int nt = 0; nt < 8; nt++) {
            int ntg = h * 8 + nt;
#pragma unroll
            for (int ks = 0; ks < 2; ks++) {
                uint2 bh = __ldg((const uint2*)(g_Weh + (ks * 16 + ntg) * 64 + lane * 2));
                uint2 bl = __ldg((const uint2*)(g_Wel + (ks * 16 + ntg) * 64 + lane * 2));
                MMA_TF32(acc[nt], ah[ks][0], ah[ks][1], ah[ks][2], ah[ks][3], bh.x, bh.y);
                MMA_TF32(acc[nt], ah[ks][0], ah[ks][1], ah[ks][2], ah[ks][3], bl.x, bl.y);
                MMA_TF32(acc[nt], al[ks][0], al[ks][1], al[ks][2], al[ks][3], bh.x, bh.y);
            }
        }
        // store emb row-major
#pragma unroll
        for (int nt = 0; nt < 8; nt++) {
            int col = h * 64 + nt * 8 + 2 * tr;
            *(float2*)(sEMB + (p * 16 + tq) * RSTR + col) =
                make_float2(acc[nt][0], acc[nt][1]);
            *(float2*)(sEMB + (p * 16 + tq + 8) * RSTR + col) =
                make_float2(acc[nt][2], acc[nt][3]);
        }
        __syncthreads();

        // ---- Phase C: epilogue, 8 edges per warp ----
#pragma unroll
        for (int i = 0; i < 8; i++) {
            int eloc = warp * 8 + i;
            int eg = e0 + eloc;
            int s = __ldg(srcp + eg);
            int d = __ldg(dstp + eg);
            float4 em = *(const float4*)(sEMB + eloc * RSTR + lane * 4);
            float4 xv = __ldg((const float4*)(x + (size_t)s * DD + lane * 4));
            float mx = fmaxf(em.x + bbv.x + xv.x, 0.f);
            float my = fmaxf(em.y + bbv.y + xv.y, 0.f);
            float mz = fmaxf(em.z + bbv.z + xv.z, 0.f);
            float mw = fmaxf(em.w + bbv.w + xv.w, 0.f);
            float* pp = g_h + (size_t)d * DD + lane * 4;
            asm volatile("red.global.add.v4.f32 [%0], {%1, %2, %3, %4};"
                         :: "l"(pp), "f"(mx), "f"(my), "f"(mz), "f"(mw) : "memory");
        }
        __syncthreads();   // sEMB/sEA safe to overwrite next iteration
    }
}

// ---------------------------------------------------------------------------
// Kernel 2: FUSED node MLP on tensor cores (R14, unchanged).
// ---------------------------------------------------------------------------
__device__ __forceinline__ void mma_gemm_pass(const uint32_t* __restrict__ gWh,
                                              const uint32_t* __restrict__ gWl,
                                              const float* __restrict__ sA,
                                              float acc[4][2][4],
                                              int tq, int tr, int wtile2, int lane) {
#pragma unroll 1
    for (int tk = 0; tk < 16; tk++) {
        uint2 bh[2], bl[2];
#pragma unroll
        for (int ni = 0; ni < 2; ni++) {
            int wbase = (tk * 16 + wtile2 + ni) * 64 + lane * 2;
            bh[ni] = __ldg((const uint2*)(gWh + wbase));
            bl[ni] = __ldg((const uint2*)(gWl + wbase));
        }
        const int kg = tk * 8;
#pragma unroll
        for (int mi = 0; mi < 4; mi++) {
            const float* ap = sA + (mi * 16 + tq) * PADW + kg + tr;
            float a0 = ap[0];
            float a1 = ap[8 * PADW];
            float a2 = ap[4];
            float a3 = ap[8 * PADW + 4];
            uint32_t ah0 = tf32_hi(a0), ah1 = tf32_hi(a1);
            uint32_t ah2 = tf32_hi(a2), ah3 = tf32_hi(a3);
            uint32_t al0 = __float_as_uint(a0 - __uint_as_float(ah0));
            uint32_t al1 = __float_as_uint(a1 - __uint_as_float(ah1));
            uint32_t al2 = __float_as_uint(a2 - __uint_as_float(ah2));
            uint32_t al3 = __float_as_uint(a3 - __uint_as_float(ah3));
#pragma unroll
            for (int ni = 0; ni < 2; ni++) {
                MMA_TF32(acc[mi][ni], ah0, ah1, ah2, ah3, bh[ni].x, bh[ni].y);
                MMA_TF32(acc[mi][ni], ah0, ah1, ah2, ah3, bl[ni].x, bl[ni].y);
                MMA_TF32(acc[mi][ni], al0, al1, al2, al3, bh[ni].x, bh[ni].y);
            }
        }
    }
}

__global__ void __launch_bounds__(256, 4)
mlp_fused_kernel(const float* __restrict__ b1, const float* __restrict__ b2) {
    extern __shared__ float sm[];
    float* sA = sm;                  // 64 x PADW (33.8KB)
    const int tid = threadIdx.x;
    const int row0 = blockIdx.x * 64;

    for (int i = tid; i < 64 * 32; i += 256) {
        int r = i >> 5, c4 = i & 31;
        float4 v = make_float4(0.f, 0.f, 0.f, 0.f);
        if (row0 + r < NN) v = ((const float4*)(g_h + (size_t)(row0 + r) * DD))[c4];
        *(float4*)(sA + r * PADW + c4 * 4) = v;
    }
    __syncthreads();

    const int warp = tid >> 5, lane = tid & 31;
    const int tq = lane >> 2;
    const int tr = lane & 3;
    const int wcol = warp * 16;
    const int wtile2 = warp * 2;

    float acc[4][2][4];
#pragma unroll
    for (int mi = 0; mi < 4; mi++)
#pragma unroll
        for (int ni = 0; ni < 2; ni++)
#pragma unroll
            for (int v = 0; v < 4; v++) acc[mi][ni][v] = 0.f;

    // ---- GEMM1 ----
    mma_gemm_pass(g_Wph, g_Wpl, sA, acc, tq, tr, wtile2, lane);
    __syncthreads();

    // epilogue 1: relu(acc + b1) -> sA
    {
        float bias[2][2];
#pragma unroll
        for (int ni = 0; ni < 2; ni++) {
            bias[ni][0] = __ldg(b1 + wcol + ni * 8 + 2 * tr);
            bias[ni][1] = __ldg(b1 + wcol + ni * 8 + 2 * tr + 1);
        }
#pragma unroll
        for (int mi = 0; mi < 4; mi++) {
#pragma unroll
            for (int ni = 0; ni < 2; ni++) {
                int col = wcol + ni * 8 + 2 * tr;
                int r = mi * 16 + tq;
                float2 v0;
                v0.x = fmaxf(acc[mi][ni][0] + bias[ni][0], 0.f);
                v0.y = fmaxf(acc[mi][ni][1] + bias[ni][1], 0.f);
                *(float2*)(sA + r * PADW + col) = v0;
                float2 v1;
                v1.x = fmaxf(acc[mi][ni][2] + bias[ni][0], 0.f);
                v1.y = fmaxf(acc[mi][ni][3] + bias[ni][1], 0.f);
                *(float2*)(sA + (r + 8) * PADW + col) = v1;
                acc[mi][ni][0] = 0.f; acc[mi][ni][1] = 0.f;
                acc[mi][ni][2] = 0.f; acc[mi][ni][3] = 0.f;
            }
        }
    }
    __syncthreads();

    // ---- GEMM2 ----
    mma_gemm_pass(g_Wph + 16384, g_Wpl + 16384, sA, acc, tq, tr, wtile2, lane);

    // epilogue 2: acc + b2 -> g_xres
    {
        float bias[2][2];
#pragma unroll
        for (int ni = 0; ni < 2; ni++) {
            bias[ni][0] = __ldg(b2 + wcol + ni * 8 + 2 * tr);
            bias[ni][1] = __ldg(b2 + wcol + ni * 8 + 2 * tr + 1);
        }
#pragma unroll
        for (int mi = 0; mi < 4; mi++) {
#pragma unroll
            for (int ni = 0; ni < 2; ni++) {
                int col = wcol + ni * 8 + 2 * tr;
                int r = row0 + mi * 16 + tq;
                if (r < NN) {
                    float2 v;
                    v.x = acc[mi][ni][0] + bias[ni][0];
                    v.y = acc[mi][ni][1] + bias[ni][1];
                    *(float2*)(g_xres + (size_t)r * DD + col) = v;
                }
                if (r + 8 < NN) {
                    float2 v;
                    v.x = acc[mi][ni][2] + bias[ni][0];
                    v.y = acc[mi][ni][3] + bias[ni][1];
                    *(float2*)(g_xres + (size_t)(r + 8) * DD + col) = v;
                }
            }
        }
    }
}

// ---------------------------------------------------------------------------
// Kernel 3: pocket pooling, atomic-free. Block = (graph b, slice s).
// ---------------------------------------------------------------------------
__global__ void pool_kernel(const float* __restrict__ mask) {
    __shared__ float sacc[8][KK * DD];
    __shared__ float scnt[8][KK];
    const int b = blockIdx.x / PS;
    const int s = blockIdx.x % PS;
    const int gs = g_gstart[b];
    const int len = g_gstart[b + 1] - gs;
    const int start = gs + (len * s) / PS;
    const int end = gs + (len * (s + 1)) / PS;

    const int wib = threadIdx.x >> 5;
    const int lane = threadIdx.x & 31;
    float* acc = sacc[wib];
    for (int i = lane; i < KK * DD; i += 32) acc[i] = 0.f;
    float cnt = 0.f;

    for (int n = start + wib; n < end; n += 8) {
        float m = (lane < KK) ? mask[(size_t)n * KK + lane] : 0.f;
        float4 xv = *(const float4*)(g_xres + (size_t)n * DD + lane * 4);
#pragma unroll
        for (int k = 0; k < KK; k++) {
            float mk = __shfl_sync(0xffffffffu, m, k);
            if (mk != 0.f) {
                float4* a = (float4*)(acc + k * DD + lane * 4);
                float4 v = *a;
                v.x += xv.x; v.y += xv.y; v.z += xv.z; v.w += xv.w;
                *a = v;
            }
        }
        cnt += m;
    }
    if (lane < KK) scnt[wib][lane] = cnt;
    __syncthreads();

    float* outp = g_part + (size_t)blockIdx.x * KK * DD;
    for (int i = threadIdx.x; i < KK * DD; i += blockDim.x) {
        float v = 0.f;
#pragma unroll
        for (int w = 0; w < 8; w++) v += sacc[w][i];
        outp[i] = v;
    }
    if (threadIdx.x < KK) {
        float c = 0.f;
#pragma unroll
        for (int w = 0; w < 8; w++) c += scnt[w][threadIdx.x];
        g_cntpart[blockIdx.x * KK + threadIdx.x] = c;
    }
}

// ---------------------------------------------------------------------------
// Kernel 3b: reduce partials -> g_psum, g_pcnt
// ---------------------------------------------------------------------------
__global__ void reduce_kernel() {
    int tid = blockIdx.x * blockDim.x + threadIdx.x;
    int stride = gridDim.x * blockDim.x;
    for (int i = tid; i < BB * KK * DD; i += stride) {
        int b = i / (KK * DD);
        int j = i % (KK * DD);
        float v = 0.f;
#pragma unroll
        for (int s = 0; s < PS; s++) v += g_part[(size_t)(b * PS + s) * KK * DD + j];
        g_psum[i] = v;
    }
    for (int i = tid; i < BB * KK; i += stride) {
        int b = i / KK;
        int k = i % KK;
        float c = 0.f;
#pragma unroll
        for (int s = 0; s < PS; s++) c += g_cntpart[(b * PS + s) * KK + k];
        g_pcnt[i] = c;
    }
}

// ---------------------------------------------------------------------------
// Kernel 4: pocket_emb = (psum/(cnt+1e-9)) @ Wv + bv. Warp per row (512 rows).
// ---------------------------------------------------------------------------
__global__ void pemb_kernel(const float* __restrict__ Wv, const float* __restrict__ bv) {
    const int lane = threadIdx.x & 31;
    const int r = blockIdx.x * (blockDim.x >> 5) + (threadIdx.x >> 5);
    if (r >= BB * KK) return;
    const float rinv = 1.f / (g_pcnt[r] + 1e-9f);
    const int c0 = lane * 4;
    float4 acc = *(const float4*)(bv + c0);
#pragma unroll 8
    for (int d = 0; d < DD; d++) {
        float a = g_psum[r * DD + d] * rinv;
        float4 w = __ldg((const float4*)(Wv + d * DD + c0));
        acc.x += a * w.x; acc.y += a * w.y; acc.z += a * w.z; acc.w += a * w.w;
    }
    *(float4*)(g_pemb + r * DD + c0) = acc;
}

// ---------------------------------------------------------------------------
// Kernel 5: residual pocket feedback + LayerNorm + ReLU. Warp per node.
// ---------------------------------------------------------------------------
__global__ void final_kernel(const float* __restrict__ mask, const int* __restrict__ batch,
                             const float* __restrict__ gamma, const float* __restrict__ beta,
                             float* __restrict__ out) {
    const int lane = threadIdx.x & 31;
    const int gw = blockIdx.x * (blockDim.x >> 5) + (threadIdx.x >> 5);
    const int tw = gridDim.x * (blockDim.x >> 5);
    const int c0 = lane * 4;
    const float4 gm = *(const float4*)(gamma + c0);
    const float4 bt = *(const float4*)(beta + c0);

    for (int n = gw; n < NN; n += tw) {
        int g = batch[n];
        float m = (lane < KK) ? mask[(size_t)n * KK + lane] : 0.f;
        float4 v = *(const float4*)(g_xres + (size_t)n * DD + c0);
        const float* pe = g_pemb + (size_t)g * KK * DD;
#pragma unroll
        for (int k = 0; k < KK; k++) {
            float mk = __shfl_sync(0xffffffffu, m, k);
            if (mk != 0.f) {
                float4 p = __ldg((const float4*)(pe + k * DD + c0));
                v.x += p.x; v.y += p.y; v.z += p.z; v.w += p.w;
            }
        }
        float s = v.x + v.y + v.z + v.w;
#pragma unroll
        for (int off = 16; off; off >>= 1) s += __shfl_xor_sync(0xffffffffu, s, off);
        float mu = s * (1.f / 128.f);
        float dx = v.x - mu, dy = v.y - mu, dz = v.z - mu, dw = v.w - mu;
        float sq = dx * dx + dy * dy + dz * dz + dw * dw;
#pragma unroll
        for (int off = 16; off; off >>= 1) sq += __shfl_xor_sync(0xffffffffu, sq, off);
        float rstd = rsqrtf(sq * (1.f / 128.f) + 1e-5f);
        float4 y;
        y.x = fmaxf(dx * rstd * gm.x + bt.x, 0.f);
        y.y = fmaxf(dy * rstd * gm.y + bt.y, 0.f);
        y.z = fmaxf(dz * rstd * gm.z + bt.z, 0.f);
        y.w = fmaxf(dw * rstd * gm.w + bt.w, 0.f);
        *(float4*)(out + (size_t)n * DD + c0) = y;
    }
}

// ---------------------------------------------------------------------------
extern "C" void kernel_launch(void* const* d_in, const int* in_sizes, int n_in,
                              void* d_out, int out_size) {
    const float* x     = (const float*)d_in[0];
    const int*   ei    = (const int*)d_in[1];
    const float* ea    = (const float*)d_in[2];
    const float* pmask = (const float*)d_in[3];
    const int*   batch = (const int*)d_in[4];
    const float* We    = (const float*)d_in[5];
    const float* be    = (const float*)d_in[6];
    const float* W1    = (const float*)d_in[7];
    const float* b1    = (const float*)d_in[8];
    const float* W2    = (const float*)d_in[9];
    const float* b2    = (const float*)d_in[10];
    const float* eps   = (const float*)d_in[11];
    const float* gamma = (const float*)d_in[12];
    const float* beta  = (const float*)d_in[13];
    const float* Wv    = (const float*)d_in[14];
    const float* bv    = (const float*)d_in[15];
    float* out = (float*)d_out;

    const int MLP_SMEM = 64 * PADW * 4;   // 33792 bytes (sA only)
    cudaFuncSetAttribute(mlp_fused_kernel, cudaFuncAttributeMaxDynamicSharedMemorySize, MLP_SMEM);

    init_kernel<<<2048, 256>>>(x, eps);
    bounds_kernel<<<(NN + 255) / 256, 256>>>(batch);
    wconv_kernel<<<64, 256>>>(W1, W2);
    econv_kernel<<<4, 256>>>(We);
    edge_kernel<<<1536, 256>>>(x, ei, ea, be);
    mlp_fused_kernel<<<(NN + 63) / 64, 256, MLP_SMEM>>>(b1, b2);
    pool_kernel<<<BB * PS, 256>>>(pmask);
    reduce_kernel<<<64, 256>>>();
    pemb_kernel<<<(BB * KK + 7) / 8, 256>>>(Wv, bv);
    final_kernel<<<2048, 256>>>(pmask, batch, gamma, beta, out);
}

// round 16
// speedup vs baseline: 1.2540x; 1.2540x over previous
#include <cuda_runtime.h>
#include <cuda_bf16.h>
#include <cstdint>

#define NN 50000
#define EE 600000
#define DD 128
#define KK 8
#define BB 64
#define ED 16
#define PS 8     // slices per graph for pooling
#define SASTR 68 // sAh/sAl row stride in u32 (bank-conflict-free: 68%32=4)

// Scratch (device globals; no runtime alloc)
__device__ float g_h[NN * DD];            // (1+eps)*x + agg
__device__ float g_xres[NN * DD];         // MLP output
__device__ float g_psum[BB * KK * DD];    // pocket sums
__device__ float g_pcnt[BB * KK];         // pocket counts
__device__ float g_pemb[BB * KK * DD];    // pocket embeddings
__device__ int   g_gstart[BB + 1];        // graph start offsets (batch sorted)
__device__ float g_part[BB * PS * KK * DD];   // pooling partials (atomic-free)
__device__ float g_cntpart[BB * PS * KK];
// Pre-split W1/W2 as packed bf16x2 hi/lo, fragment-major for mma.m16n8k16:
// [w][ktile8][ntile16][lane32][slot2]  (slot0 = b0 reg, slot1 = b1 reg)
__device__ uint32_t g_Wbh[2 * 8192];
__device__ uint32_t g_Wbl[2 * 8192];

// packed-fp32 helpers (FFMA2: exact fp32 math, 2x fma-pipe throughput)
#define FMA2(acc, a2, w2) \
    asm("fma.rn.f32x2 %0, %1, %2, %0;" : "+l"(acc) : "l"(a2), "l"(w2))
#define DUP2(a2, f) \
    asm("mov.b64 %0, {%1, %1};" : "=l"(a2) : "f"(f))
#define PACK2(p, lo, hi) \
    asm("mov.b64 %0, {%1, %2};" : "=l"(p) : "f"(lo), "f"(hi))
#define UNPACK2(lo, hi, p) \
    asm("mov.b64 {%0, %1}, %2;" : "=f"(lo), "=f"(hi) : "l"(p))

// bf16 helpers
__device__ __forceinline__ uint32_t bfpack(__nv_bfloat16 lo, __nv_bfloat16 hi) {
    __nv_bfloat162 t;
    t.x = lo; t.y = hi;
    return *reinterpret_cast<uint32_t*>(&t);
}
#define MMA_BF16(d, a0, a1, a2, a3, b0, b1) \
    asm volatile("mma.sync.aligned.m16n8k16.row.col.f32.bf16.bf16.f32 " \
                 "{%0,%1,%2,%3}, {%4,%5,%6,%7}, {%8,%9}, {%0,%1,%2,%3};" \
                 : "+f"(d[0]), "+f"(d[1]), "+f"(d[2]), "+f"(d[3]) \
                 : "r"(a0), "r"(a1), "r"(a2), "r"(a3), "r"(b0), "r"(b1))

// ---------------------------------------------------------------------------
// Kernel 0: g_h = (1+eps)*x
// ---------------------------------------------------------------------------
__global__ void init_kernel(const float* __restrict__ x, const float* __restrict__ epsp) {
    const float c = 1.0f + epsp[0];
    int tid = blockIdx.x * blockDim.x + threadIdx.x;
    int stride = gridDim.x * blockDim.x;
    const float4* x4 = (const float4*)x;
    float4* h4 = (float4*)g_h;
    for (int i = tid; i < NN * DD / 4; i += stride) {
        float4 v = x4[i];
        v.x *= c; v.y *= c; v.z *= c; v.w *= c;
        h4[i] = v;
    }
}

// ---------------------------------------------------------------------------
// Kernel 0b: graph boundary offsets from sorted batch
// ---------------------------------------------------------------------------
__global__ void bounds_kernel(const int* __restrict__ batch) {
    int n = blockIdx.x * blockDim.x + threadIdx.x;
    if (n >= NN) return;
    int b1 = batch[n];
    int b0 = (n == 0) ? -1 : batch[n - 1];
    for (int g = b0 + 1; g <= b1; g++) g_gstart[g] = n;
    if (n == NN - 1)
        for (int g = b1 + 1; g <= BB; g++) g_gstart[g] = NN;
}

// ---------------------------------------------------------------------------
// Kernel 0c: split W1/W2 into packed bf16x2 hi/lo, m16n8k16 b-frag layout:
//   b0 = {W[k0+2tr][n], W[k0+2tr+1][n]}, b1 = {W[k0+2tr+8][n], W[k0+2tr+9][n]}
//   with n = tn*8 + tq, k0 = tk*16.
// ---------------------------------------------------------------------------
__global__ void wconv_kernel(const float* __restrict__ W1, const float* __restrict__ W2) {
    int idx = blockIdx.x * blockDim.x + threadIdx.x;   // over 2*8*16*32 = 8192
    if (idx >= 2 * 8 * 16 * 32) return;
    int w = idx >> 12;
    int rest = idx & 4095;
    int tk = rest >> 9;
    int tn = (rest >> 5) & 15;
    int lane = rest & 31;
    int tq = lane >> 2, tr = lane & 3;
    const float* W = (w == 0) ? W1 : W2;
    const int n = tn * 8 + tq;
    const int k0 = tk * 16;
    float v00 = W[(k0 + 2 * tr) * DD + n];
    float v01 = W[(k0 + 2 * tr + 1) * DD + n];
    float v10 = W[(k0 + 2 * tr + 8) * DD + n];
    float v11 = W[(k0 + 2 * tr + 9) * DD + n];
    __nv_bfloat16 h00 = __float2bfloat16(v00), h01 = __float2bfloat16(v01);
    __nv_bfloat16 h10 = __float2bfloat16(v10), h11 = __float2bfloat16(v11);
    __nv_bfloat16 l00 = __float2bfloat16(v00 - __bfloat162float(h00));
    __nv_bfloat16 l01 = __float2bfloat16(v01 - __bfloat162float(h01));
    __nv_bfloat16 l10 = __float2bfloat16(v10 - __bfloat162float(h10));
    __nv_bfloat16 l11 = __float2bfloat16(v11 - __bfloat162float(h11));
    int base = w * 8192 + (tk * 16 + tn) * 64 + lane * 2;
    g_Wbh[base]     = bfpack(h00, h01);
    g_Wbh[base + 1] = bfpack(h10, h11);
    g_Wbl[base]     = bfpack(l00, l01);
    g_Wbl[base + 1] = bfpack(l10, l11);
}

// ---------------------------------------------------------------------------
// Kernel 1: edges. Warp processes 8 edges per iteration (R13/R14 winner).
// ---------------------------------------------------------------------------
__global__ void __launch_bounds__(256)
edge_kernel(const float* __restrict__ x,
            const int* __restrict__ ei,
            const float* __restrict__ ea,
            const float* __restrict__ We,
            const float* __restrict__ be) {
    __shared__ float sWe[ED * DD];
    __shared__ float sbe[DD];
    for (int i = threadIdx.x; i < ED * DD / 4; i += blockDim.x)
        ((float4*)sWe)[i] = ((const float4*)We)[i];
    if (threadIdx.x < DD) sbe[threadIdx.x] = be[threadIdx.x];
    __syncthreads();

    const int lane = threadIdx.x & 31;
    const int warp = blockIdx.x * (blockDim.x >> 5) + (threadIdx.x >> 5);
    const int nwarps = gridDim.x * (blockDim.x >> 5);
    const int* __restrict__ srcp = ei;
    const int* __restrict__ dstp = ei + EE;
    const int c0 = lane * 4;

    float4 bbv = *(const float4*)(&sbe[c0]);
    unsigned long long bp0, bp1;
    PACK2(bp0, bbv.x, bbv.y);
    PACK2(bp1, bbv.z, bbv.w);

    const int NG = EE / 8;   // 75000 groups of 8 edges
    for (int g = warp; g < NG; g += nwarps) {
        const int e0 = g * 8;
        const float* eab = ea + (size_t)e0 * ED;
        float r[4];
        r[0] = __ldg(eab + lane);
        r[1] = __ldg(eab + lane + 32);
        r[2] = __ldg(eab + lane + 64);
        r[3] = __ldg(eab + lane + 96);

        unsigned long long acc[8][2];
#pragma unroll
        for (int i = 0; i < 8; i++) { acc[i][0] = bp0; acc[i][1] = bp1; }

#pragma unroll
        for (int j = 0; j < ED; j++) {
            ulonglong2 w = *(const ulonglong2*)(&sWe[j * DD + c0]);
#pragma unroll
            for (int i = 0; i < 8; i++) {
                float a = __shfl_sync(0xffffffffu, r[i >> 1], ((i & 1) << 4) + j);
                unsigned long long t;
                DUP2(t, a);
                FMA2(acc[i][0], t, w.x);
                FMA2(acc[i][1], t, w.y);
            }
        }

#pragma unroll
        for (int i = 0; i < 8; i++) {
            int s = __ldg(srcp + e0 + i);
            int d = __ldg(dstp + e0 + i);
            float ex, ey, ez, ew;
            UNPACK2(ex, ey, acc[i][0]);
            UNPACK2(ez, ew, acc[i][1]);
            float4 xv = __ldg((const float4*)(x + (size_t)s * DD + c0));
            float mx = fmaxf(ex + xv.x, 0.f);
            float my = fmaxf(ey + xv.y, 0.f);
            float mz = fmaxf(ez + xv.z, 0.f);
            float mw = fmaxf(ew + xv.w, 0.f);
            float* p = g_h + (size_t)d * DD + c0;
            asm volatile("red.global.add.v4.f32 [%0], {%1, %2, %3, %4};"
                         :: "l"(p), "f"(mx), "f"(my), "f"(mz), "f"(mw) : "memory");
        }
    }
}

// ---------------------------------------------------------------------------
// Kernel 2: FUSED node MLP on tensor cores, bf16 double-split (3-term),
// mma.m16n8k16. A pre-split to packed bf16x2 hi/lo in smem (fill/epilogue
// only); W pre-split in global (wconv). Inner loop: pure LDS/LDG + MMA.
// MMA count halved vs 3xTF32 path; no cvt in loop. Error ~2^-18/product.
// ---------------------------------------------------------------------------
__device__ __forceinline__ void mma_gemm_pass(const uint32_t* __restrict__ gWh,
                                              const uint32_t* __restrict__ gWl,
                                              const uint32_t* __restrict__ sAh,
                                              const uint32_t* __restrict__ sAl,
                                              float acc[4][2][4],
                                              int tq, int tr, int wtile2, int lane) {
#pragma unroll
    for (int tk = 0; tk < 8; tk++) {
        uint2 bh[2], bl[2];
#pragma unroll
        for (int ni = 0; ni < 2; ni++) {
            int wbase = (tk * 16 + wtile2 + ni) * 64 + lane * 2;
            bh[ni] = __ldg((const uint2*)(gWh + wbase));
            bl[ni] = __ldg((const uint2*)(gWl + wbase));
        }
#pragma unroll
        for (int mi = 0; mi < 4; mi++) {
            const int r0 = (mi * 16 + tq) * SASTR + tk * 8 + tr;
            const int r1 = (mi * 16 + tq + 8) * SASTR + tk * 8 + tr;
            uint32_t ah0 = sAh[r0], ah1 = sAh[r1];
            uint32_t ah2 = sAh[r0 + 4], ah3 = sAh[r1 + 4];
            uint32_t al0 = sAl[r0], al1 = sAl[r1];
            uint32_t al2 = sAl[r0 + 4], al3 = sAl[r1 + 4];
#pragma unroll
            for (int ni = 0; ni < 2; ni++) {
                MMA_BF16(acc[mi][ni], ah0, ah1, ah2, ah3, bh[ni].x, bh[ni].y);
                MMA_BF16(acc[mi][ni], ah0, ah1, ah2, ah3, bl[ni].x, bl[ni].y);
                MMA_BF16(acc[mi][ni], al0, al1, al2, al3, bh[ni].x, bh[ni].y);
            }
        }
    }
}

__global__ void __launch_bounds__(256, 4)
mlp_fused_kernel(const float* __restrict__ b1, const float* __restrict__ b2) {
    extern __shared__ uint32_t smu[];
    uint32_t* sAh = smu;                  // 64 x SASTR u32 (17.4KB)
    uint32_t* sAl = smu + 64 * SASTR;     // 64 x SASTR u32 (17.4KB)
    const int tid = threadIdx.x;
    const int row0 = blockIdx.x * 64;

    // fill: load fp32 rows, split to bf16 hi/lo, store packed pairs (k-major)
    for (int i = tid; i < 64 * 32; i += 256) {
        int r = i >> 5, c4 = i & 31;
        float4 v = make_float4(0.f, 0.f, 0.f, 0.f);
        if (row0 + r < NN) v = ((const float4*)(g_h + (size_t)(row0 + r) * DD))[c4];
        __nv_bfloat16 hx = __float2bfloat16(v.x), hy = __float2bfloat16(v.y);
        __nv_bfloat16 hz = __float2bfloat16(v.z), hw = __float2bfloat16(v.w);
        __nv_bfloat16 lx = __float2bfloat16(v.x - __bfloat162float(hx));
        __nv_bfloat16 ly = __float2bfloat16(v.y - __bfloat162float(hy));
        __nv_bfloat16 lz = __float2bfloat16(v.z - __bfloat162float(hz));
        __nv_bfloat16 lw = __float2bfloat16(v.w - __bfloat162float(hw));
        int base = r * SASTR + 2 * c4;
        sAh[base]     = bfpack(hx, hy);
        sAh[base + 1] = bfpack(hz, hw);
        sAl[base]     = bfpack(lx, ly);
        sAl[base + 1] = bfpack(lz, lw);
    }
    __syncthreads();

    const int warp = tid >> 5, lane = tid & 31;
    const int tq = lane >> 2;
    const int tr = lane & 3;
    const int wcol = warp * 16;
    const int wtile2 = warp * 2;

    float acc[4][2][4];
#pragma unroll
    for (int mi = 0; mi < 4; mi++)
#pragma unroll
        for (int ni = 0; ni < 2; ni++)
#pragma unroll
            for (int v = 0; v < 4; v++) acc[mi][ni][v] = 0.f;

    // ---- GEMM1 ----
    mma_gemm_pass(g_Wbh, g_Wbl, sAh, sAl, acc, tq, tr, wtile2, lane);
    __syncthreads();   // all warps done reading sA before epilogue overwrites it

    // epilogue 1: relu(acc + b1) -> sAh/sAl (packed bf16 pairs, col pair = word)
    {
        float bias[2][2];
#pragma unroll
        for (int ni = 0; ni < 2; ni++) {
            bias[ni][0] = __ldg(b1 + wcol + ni * 8 + 2 * tr);
            bias[ni][1] = __ldg(b1 + wcol + ni * 8 + 2 * tr + 1);
        }
#pragma unroll
        for (int mi = 0; mi < 4; mi++) {
#pragma unroll
            for (int ni = 0; ni < 2; ni++) {
                int wd = warp * 8 + ni * 4 + tr;   // word index of col pair
                int ra = mi * 16 + tq, rb = ra + 8;
                float v0 = fmaxf(acc[mi][ni][0] + bias[ni][0], 0.f);
                float v1 = fmaxf(acc[mi][ni][1] + bias[ni][1], 0.f);
                float v2 = fmaxf(acc[mi][ni][2] + bias[ni][0], 0.f);
                float v3 = fmaxf(acc[mi][ni][3] + bias[ni][1], 0.f);
                __nv_bfloat16 h0 = __float2bfloat16(v0), h1 = __float2bfloat16(v1);
                __nv_bfloat16 h2 = __float2bfloat16(v2), h3 = __float2bfloat16(v3);
                sAh[ra * SASTR + wd] = bfpack(h0, h1);
                sAh[rb * SASTR + wd] = bfpack(h2, h3);
                sAl[ra * SASTR + wd] = bfpack(
                    __float2bfloat16(v0 - __bfloat162float(h0)),
                    __float2bfloat16(v1 - __bfloat162float(h1)));
                sAl[rb * SASTR + wd] = bfpack(
                    __float2bfloat16(v2 - __bfloat162float(h2)),
                    __float2bfloat16(v3 - __bfloat162float(h3)));
                acc[mi][ni][0] = 0.f; acc[mi][ni][1] = 0.f;
                acc[mi][ni][2] = 0.f; acc[mi][ni][3] = 0.f;
            }
        }
    }
    __syncthreads();   // epilogue writes visible before GEMM2 reads sA

    // ---- GEMM2 ----
    mma_gemm_pass(g_Wbh + 8192, g_Wbl + 8192, sAh, sAl, acc, tq, tr, wtile2, lane);

    // epilogue 2: acc + b2 -> g_xres (fp32)
    {
        float bias[2][2];
#pragma unroll
        for (int ni = 0; ni < 2; ni++) {
            bias[ni][0] = __ldg(b2 + wcol + ni * 8 + 2 * tr);
            bias[ni][1] = __ldg(b2 + wcol + ni * 8 + 2 * tr + 1);
        }
#pragma unroll
        for (int mi = 0; mi < 4; mi++) {
#pragma unroll
            for (int ni = 0; ni < 2; ni++) {
                int col = wcol + ni * 8 + 2 * tr;
                int r = row0 + mi * 16 + tq;
                if (r < NN) {
                    float2 v;
                    v.x = acc[mi][ni][0] + bias[ni][0];
                    v.y = acc[mi][ni][1] + bias[ni][1];
                    *(float2*)(g_xres + (size_t)r * DD + col) = v;
                }
                if (r + 8 < NN) {
                    float2 v;
                    v.x = acc[mi][ni][2] + bias[ni][0];
                    v.y = acc[mi][ni][3] + bias[ni][1];
                    *(float2*)(g_xres + (size_t)(r + 8) * DD + col) = v;
                }
            }
        }
    }
}

// ---------------------------------------------------------------------------
// Kernel 3: pocket pooling, atomic-free. Block = (graph b, slice s).
// ---------------------------------------------------------------------------
__global__ void pool_kernel(const float* __restrict__ mask) {
    __shared__ float sacc[8][KK * DD];
    __shared__ float scnt[8][KK];
    const int b = blockIdx.x / PS;
    const int s = blockIdx.x % PS;
    const int gs = g_gstart[b];
    const int len = g_gstart[b + 1] - gs;
    const int start = gs + (len * s) / PS;
    const int end = gs + (len * (s + 1)) / PS;

    const int wib = threadIdx.x >> 5;
    const int lane = threadIdx.x & 31;
    float* acc = sacc[wib];
    for (int i = lane; i < KK * DD; i += 32) acc[i] = 0.f;
    float cnt = 0.f;

    for (int n = start + wib; n < end; n += 8) {
        float m = (lane < KK) ? mask[(size_t)n * KK + lane] : 0.f;
        float4 xv = *(const float4*)(g_xres + (size_t)n * DD + lane * 4);
#pragma unroll
        for (int k = 0; k < KK; k++) {
            float mk = __shfl_sync(0xffffffffu, m, k);
            if (mk != 0.f) {
                float4* a = (float4*)(acc + k * DD + lane * 4);
                float4 v = *a;
                v.x += xv.x; v.y += xv.y; v.z += xv.z; v.w += xv.w;
                *a = v;
            }
        }
        cnt += m;
    }
    if (lane < KK) scnt[wib][lane] = cnt;
    __syncthreads();

    float* outp = g_part + (size_t)blockIdx.x * KK * DD;
    for (int i = threadIdx.x; i < KK * DD; i += blockDim.x) {
        float v = 0.f;
#pragma unroll
        for (int w = 0; w < 8; w++) v += sacc[w][i];
        outp[i] = v;
    }
    if (threadIdx.x < KK) {
        float c = 0.f;
#pragma unroll
        for (int w = 0; w < 8; w++) c += scnt[w][threadIdx.x];
        g_cntpart[blockIdx.x * KK + threadIdx.x] = c;
    }
}

// ---------------------------------------------------------------------------
// Kernel 3b: reduce partials -> g_psum, g_pcnt
// ---------------------------------------------------------------------------
__global__ void reduce_kernel() {
    int tid = blockIdx.x * blockDim.x + threadIdx.x;
    int stride = gridDim.x * blockDim.x;
    for (int i = tid; i < BB * KK * DD; i += stride) {
        int b = i / (KK * DD);
        int j = i % (KK * DD);
        float v = 0.f;
#pragma unroll
        for (int s = 0; s < PS; s++) v += g_part[(size_t)(b * PS + s) * KK * DD + j];
        g_psum[i] = v;
    }
    for (int i = tid; i < BB * KK; i += stride) {
        int b = i / KK;
        int k = i % KK;
        float c = 0.f;
#pragma unroll
        for (int s = 0; s < PS; s++) c += g_cntpart[(b * PS + s) * KK + k];
        g_pcnt[i] = c;
    }
}

// ---------------------------------------------------------------------------
// Kernel 4: pocket_emb = (psum/(cnt+1e-9)) @ Wv + bv. Warp per row (512 rows).
// ---------------------------------------------------------------------------
__global__ void pemb_kernel(const float* __restrict__ Wv, const float* __restrict__ bv) {
    const int lane = threadIdx.x & 31;
    const int r = blockIdx.x * (blockDim.x >> 5) + (threadIdx.x >> 5);
    if (r >= BB * KK) return;
    const float rinv = 1.f / (g_pcnt[r] + 1e-9f);
    const int c0 = lane * 4;
    float4 acc = *(const float4*)(bv + c0);
#pragma unroll 8
    for (int d = 0; d < DD; d++) {
        float a = g_psum[r * DD + d] * rinv;
        float4 w = __ldg((const float4*)(Wv + d * DD + c0));
        acc.x += a * w.x; acc.y += a * w.y; acc.z += a * w.z; acc.w += a * w.w;
    }
    *(float4*)(g_pemb + r * DD + c0) = acc;
}

// ---------------------------------------------------------------------------
// Kernel 5: residual pocket feedback + LayerNorm + ReLU. Warp per node.
// ---------------------------------------------------------------------------
__global__ void final_kernel(const float* __restrict__ mask, const int* __restrict__ batch,
                             const float* __restrict__ gamma, const float* __restrict__ beta,
                             float* __restrict__ out) {
    const int lane = threadIdx.x & 31;
    const int gw = blockIdx.x * (blockDim.x >> 5) + (threadIdx.x >> 5);
    const int tw = gridDim.x * (blockDim.x >> 5);
    const int c0 = lane * 4;
    const float4 gm = *(const float4*)(gamma + c0);
    const float4 bt = *(const float4*)(beta + c0);

    for (int n = gw; n < NN; n += tw) {
        int g = batch[n];
        float m = (lane < KK) ? mask[(size_t)n * KK + lane] : 0.f;
        float4 v = *(const float4*)(g_xres + (size_t)n * DD + c0);
        const float* pe = g_pemb + (size_t)g * KK * DD;
#pragma unroll
        for (int k = 0; k < KK; k++) {
            float mk = __shfl_sync(0xffffffffu, m, k);
            if (mk != 0.f) {
                float4 p = __ldg((const float4*)(pe + k * DD + c0));
                v.x += p.x; v.y += p.y; v.z += p.z; v.w += p.w;
            }
        }
        float s = v.x + v.y + v.z + v.w;
#pragma unroll
        for (int off = 16; off; off >>= 1) s += __shfl_xor_sync(0xffffffffu, s, off);
        float mu = s * (1.f / 128.f);
        float dx = v.x - mu, dy = v.y - mu, dz = v.z - mu, dw = v.w - mu;
        float sq = dx * dx + dy * dy + dz * dz + dw * dw;
#pragma unroll
        for (int off = 16; off; off >>= 1) sq += __shfl_xor_sync(0xffffffffu, sq, off);
        float rstd = rsqrtf(sq * (1.f / 128.f) + 1e-5f);
        float4 y;
        y.x = fmaxf(dx * rstd * gm.x + bt.x, 0.f);
        y.y = fmaxf(dy * rstd * gm.y + bt.y, 0.f);
        y.z = fmaxf(dz * rstd * gm.z + bt.z, 0.f);
        y.w = fmaxf(dw * rstd * gm.w + bt.w, 0.f);
        *(float4*)(out + (size_t)n * DD + c0) = y;
    }
}

// ---------------------------------------------------------------------------
extern "C" void kernel_launch(void* const* d_in, const int* in_sizes, int n_in,
                              void* d_out, int out_size) {
    const float* x     = (const float*)d_in[0];
    const int*   ei    = (const int*)d_in[1];
    const float* ea    = (const float*)d_in[2];
    const float* pmask = (const float*)d_in[3];
    const int*   batch = (const int*)d_in[4];
    const float* We    = (const float*)d_in[5];
    const float* be    = (const float*)d_in[6];
    const float* W1    = (const float*)d_in[7];
    const float* b1    = (const float*)d_in[8];
    const float* W2    = (const float*)d_in[9];
    const float* b2    = (const float*)d_in[10];
    const float* eps   = (const float*)d_in[11];
    const float* gamma = (const float*)d_in[12];
    const float* beta  = (const float*)d_in[13];
    const float* Wv    = (const float*)d_in[14];
    const float* bv    = (const float*)d_in[15];
    float* out = (float*)d_out;

    const int MLP_SMEM = 2 * 64 * SASTR * 4;   // 34816 bytes (sAh + sAl)
    cudaFuncSetAttribute(mlp_fused_kernel, cudaFuncAttributeMaxDynamicSharedMemorySize, MLP_SMEM);

    init_kernel<<<2048, 256>>>(x, eps);
    bounds_kernel<<<(NN + 255) / 256, 256>>>(batch);
    wconv_kernel<<<32, 256>>>(W1, W2);
    edge_kernel<<<4096, 256>>>(x, ei, ea, We, be);
    mlp_fused_kernel<<<(NN + 63) / 64, 256, MLP_SMEM>>>(b1, b2);
    pool_kernel<<<BB * PS, 256>>>(pmask);
    reduce_kernel<<<64, 256>>>();
    pemb_kernel<<<(BB * KK + 7) / 8, 256>>>(Wv, bv);
    final_kernel<<<2048, 256>>>(pmask, batch, gamma, beta, out);
}

// round 17
// speedup vs baseline: 1.2856x; 1.0252x over previous
#include <cuda_runtime.h>
#include <cuda_bf16.h>
#include <cstdint>

#define NN 50000
#define EE 600000
#define DD 128
#define KK 8
#define BB 64
#define ED 16
#define PS 8     // slices per graph for pooling
#define SASTR 68 // sAh/sAl row stride in u32 (bank-conflict-free: 68%32=4)

// Scratch (device globals; no runtime alloc)
__device__ float g_h[NN * DD];            // (1+eps)*x + agg
__device__ float g_xres[NN * DD];         // MLP output
__device__ float g_psum[BB * KK * DD];    // pocket sums
__device__ float g_pcnt[BB * KK];         // pocket counts
__device__ float g_pemb[BB * KK * DD];    // pocket embeddings
__device__ int   g_gstart[BB + 1];        // graph start offsets (batch sorted)
__device__ float g_part[BB * PS * KK * DD];   // pooling partials (atomic-free)
__device__ float g_cntpart[BB * PS * KK];
// Pre-split W1/W2 as packed bf16x2 hi/lo, fragment-major for mma.m16n8k16:
// [w][ktile8][ntile16][lane32][slot2]  (slot0 = b0 reg, slot1 = b1 reg)
__device__ uint32_t g_Wbh[2 * 8192];
__device__ uint32_t g_Wbl[2 * 8192];

// packed-fp32 helpers (FFMA2: exact fp32 math, 2x fma-pipe throughput)
#define FMA2(acc, a2, w2) \
    asm("fma.rn.f32x2 %0, %1, %2, %0;" : "+l"(acc) : "l"(a2), "l"(w2))
#define DUP2(a2, f) \
    asm("mov.b64 %0, {%1, %1};" : "=l"(a2) : "f"(f))
#define PACK2(p, lo, hi) \
    asm("mov.b64 %0, {%1, %2};" : "=l"(p) : "f"(lo), "f"(hi))
#define UNPACK2(lo, hi, p) \
    asm("mov.b64 {%0, %1}, %2;" : "=f"(lo), "=f"(hi) : "l"(p))

// bf16 helpers
__device__ __forceinline__ uint32_t bfpack(__nv_bfloat16 lo, __nv_bfloat16 hi) {
    __nv_bfloat162 t;
    t.x = lo; t.y = hi;
    return *reinterpret_cast<uint32_t*>(&t);
}
#define MMA_BF16(d, a0, a1, a2, a3, b0, b1) \
    asm volatile("mma.sync.aligned.m16n8k16.row.col.f32.bf16.bf16.f32 " \
                 "{%0,%1,%2,%3}, {%4,%5,%6,%7}, {%8,%9}, {%0,%1,%2,%3};" \
                 : "+f"(d[0]), "+f"(d[1]), "+f"(d[2]), "+f"(d[3]) \
                 : "r"(a0), "r"(a1), "r"(a2), "r"(a3), "r"(b0), "r"(b1))

// ---------------------------------------------------------------------------
// Kernel 0: g_h = (1+eps)*x
// ---------------------------------------------------------------------------
__global__ void init_kernel(const float* __restrict__ x, const float* __restrict__ epsp) {
    const float c = 1.0f + epsp[0];
    int tid = blockIdx.x * blockDim.x + threadIdx.x;
    int stride = gridDim.x * blockDim.x;
    const float4* x4 = (const float4*)x;
    float4* h4 = (float4*)g_h;
    for (int i = tid; i < NN * DD / 4; i += stride) {
        float4 v = x4[i];
        v.x *= c; v.y *= c; v.z *= c; v.w *= c;
        h4[i] = v;
    }
}

// ---------------------------------------------------------------------------
// Kernel 0b: graph boundary offsets from sorted batch
// ---------------------------------------------------------------------------
__global__ void bounds_kernel(const int* __restrict__ batch) {
    int n = blockIdx.x * blockDim.x + threadIdx.x;
    if (n >= NN) return;
    int b1 = batch[n];
    int b0 = (n == 0) ? -1 : batch[n - 1];
    for (int g = b0 + 1; g <= b1; g++) g_gstart[g] = n;
    if (n == NN - 1)
        for (int g = b1 + 1; g <= BB; g++) g_gstart[g] = NN;
}

// ---------------------------------------------------------------------------
// Kernel 0c: split W1/W2 into packed bf16x2 hi/lo, m16n8k16 b-frag layout
// (verified R16: rel_err 4.5e-6)
// ---------------------------------------------------------------------------
__global__ void wconv_kernel(const float* __restrict__ W1, const float* __restrict__ W2) {
    int idx = blockIdx.x * blockDim.x + threadIdx.x;   // over 2*8*16*32 = 8192
    if (idx >= 2 * 8 * 16 * 32) return;
    int w = idx >> 12;
    int rest = idx & 4095;
    int tk = rest >> 9;
    int tn = (rest >> 5) & 15;
    int lane = rest & 31;
    int tq = lane >> 2, tr = lane & 3;
    const float* W = (w == 0) ? W1 : W2;
    const int n = tn * 8 + tq;
    const int k0 = tk * 16;
    float v00 = W[(k0 + 2 * tr) * DD + n];
    float v01 = W[(k0 + 2 * tr + 1) * DD + n];
    float v10 = W[(k0 + 2 * tr + 8) * DD + n];
    float v11 = W[(k0 + 2 * tr + 9) * DD + n];
    __nv_bfloat16 h00 = __float2bfloat16(v00), h01 = __float2bfloat16(v01);
    __nv_bfloat16 h10 = __float2bfloat16(v10), h11 = __float2bfloat16(v11);
    __nv_bfloat16 l00 = __float2bfloat16(v00 - __bfloat162float(h00));
    __nv_bfloat16 l01 = __float2bfloat16(v01 - __bfloat162float(h01));
    __nv_bfloat16 l10 = __float2bfloat16(v10 - __bfloat162float(h10));
    __nv_bfloat16 l11 = __float2bfloat16(v11 - __bfloat162float(h11));
    int base = w * 8192 + (tk * 16 + tn) * 64 + lane * 2;
    g_Wbh[base]     = bfpack(h00, h01);
    g_Wbh[base + 1] = bfpack(h10, h11);
    g_Wbl[base]     = bfpack(l00, l01);
    g_Wbl[base + 1] = bfpack(l10, l11);
}

// ---------------------------------------------------------------------------
// Kernel 1: edges. Warp processes 8 edges per iteration (R13 winner) with
// __launch_bounds__(256, 4): caps regs at 64 -> 4 blocks/SM instead of 3.
// Kernel is latency-bound (issue 37.6%, L1 75.9%, nothing saturated) and
// needs the extra warps for latency hiding.
// ---------------------------------------------------------------------------
__global__ void __launch_bounds__(256, 4)
edge_kernel(const float* __restrict__ x,
            const int* __restrict__ ei,
            const float* __restrict__ ea,
            const float* __restrict__ We,
            const float* __restrict__ be) {
    __shared__ float sWe[ED * DD];
    __shared__ float sbe[DD];
    for (int i = threadIdx.x; i < ED * DD / 4; i += blockDim.x)
        ((float4*)sWe)[i] = ((const float4*)We)[i];
    if (threadIdx.x < DD) sbe[threadIdx.x] = be[threadIdx.x];
    __syncthreads();

    const int lane = threadIdx.x & 31;
    const int warp = blockIdx.x * (blockDim.x >> 5) + (threadIdx.x >> 5);
    const int nwarps = gridDim.x * (blockDim.x >> 5);
    const int* __restrict__ srcp = ei;
    const int* __restrict__ dstp = ei + EE;
    const int c0 = lane * 4;

    float4 bbv = *(const float4*)(&sbe[c0]);
    unsigned long long bp0, bp1;
    PACK2(bp0, bbv.x, bbv.y);
    PACK2(bp1, bbv.z, bbv.w);

    const int NG = EE / 8;   // 75000 groups of 8 edges
    for (int g = warp; g < NG; g += nwarps) {
        const int e0 = g * 8;
        const float* eab = ea + (size_t)e0 * ED;
        float r[4];
        r[0] = __ldg(eab + lane);
        r[1] = __ldg(eab + lane + 32);
        r[2] = __ldg(eab + lane + 64);
        r[3] = __ldg(eab + lane + 96);

        unsigned long long acc[8][2];
#pragma unroll
        for (int i = 0; i < 8; i++) { acc[i][0] = bp0; acc[i][1] = bp1; }

#pragma unroll
        for (int j = 0; j < ED; j++) {
            ulonglong2 w = *(const ulonglong2*)(&sWe[j * DD + c0]);
#pragma unroll
            for (int i = 0; i < 8; i++) {
                float a = __shfl_sync(0xffffffffu, r[i >> 1], ((i & 1) << 4) + j);
                unsigned long long t;
                DUP2(t, a);
                FMA2(acc[i][0], t, w.x);
                FMA2(acc[i][1], t, w.y);
            }
        }

#pragma unroll
        for (int i = 0; i < 8; i++) {
            int s = __ldg(srcp + e0 + i);
            int d = __ldg(dstp + e0 + i);
            float ex, ey, ez, ew;
            UNPACK2(ex, ey, acc[i][0]);
            UNPACK2(ez, ew, acc[i][1]);
            float4 xv = __ldg((const float4*)(x + (size_t)s * DD + c0));
            float mx = fmaxf(ex + xv.x, 0.f);
            float my = fmaxf(ey + xv.y, 0.f);
            float mz = fmaxf(ez + xv.z, 0.f);
            float mw = fmaxf(ew + xv.w, 0.f);
            float* p = g_h + (size_t)d * DD + c0;
            asm volatile("red.global.add.v4.f32 [%0], {%1, %2, %3, %4};"
                         :: "l"(p), "f"(mx), "f"(my), "f"(mz), "f"(mw) : "memory");
        }
    }
}

// ---------------------------------------------------------------------------
// Kernel 2: FUSED node MLP on tensor cores, bf16 double-split (R16 winner).
// ---------------------------------------------------------------------------
__device__ __forceinline__ void mma_gemm_pass(const uint32_t* __restrict__ gWh,
                                              const uint32_t* __restrict__ gWl,
                                              const uint32_t* __restrict__ sAh,
                                              const uint32_t* __restrict__ sAl,
                                              float acc[4][2][4],
                                              int tq, int tr, int wtile2, int lane) {
#pragma unroll
    for (int tk = 0; tk < 8; tk++) {
        uint2 bh[2], bl[2];
#pragma unroll
        for (int ni = 0; ni < 2; ni++) {
            int wbase = (tk * 16 + wtile2 + ni) * 64 + lane * 2;
            bh[ni] = __ldg((const uint2*)(gWh + wbase));
            bl[ni] = __ldg((const uint2*)(gWl + wbase));
        }
#pragma unroll
        for (int mi = 0; mi < 4; mi++) {
            const int r0 = (mi * 16 + tq) * SASTR + tk * 8 + tr;
            const int r1 = (mi * 16 + tq + 8) * SASTR + tk * 8 + tr;
            uint32_t ah0 = sAh[r0], ah1 = sAh[r1];
            uint32_t ah2 = sAh[r0 + 4], ah3 = sAh[r1 + 4];
            uint32_t al0 = sAl[r0], al1 = sAl[r1];
            uint32_t al2 = sAl[r0 + 4], al3 = sAl[r1 + 4];
#pragma unroll
            for (int ni = 0; ni < 2; ni++) {
                MMA_BF16(acc[mi][ni], ah0, ah1, ah2, ah3, bh[ni].x, bh[ni].y);
                MMA_BF16(acc[mi][ni], ah0, ah1, ah2, ah3, bl[ni].x, bl[ni].y);
                MMA_BF16(acc[mi][ni], al0, al1, al2, al3, bh[ni].x, bh[ni].y);
            }
        }
    }
}

__global__ void __launch_bounds__(256, 4)
mlp_fused_kernel(const float* __restrict__ b1, const float* __restrict__ b2) {
    extern __shared__ uint32_t smu[];
    uint32_t* sAh = smu;                  // 64 x SASTR u32 (17.4KB)
    uint32_t* sAl = smu + 64 * SASTR;     // 64 x SASTR u32 (17.4KB)
    const int tid = threadIdx.x;
    const int row0 = blockIdx.x * 64;

    // fill: load fp32 rows, split to bf16 hi/lo, store packed pairs (k-major)
    for (int i = tid; i < 64 * 32; i += 256) {
        int r = i >> 5, c4 = i & 31;
        float4 v = make_float4(0.f, 0.f, 0.f, 0.f);
        if (row0 + r < NN) v = ((const float4*)(g_h + (size_t)(row0 + r) * DD))[c4];
        __nv_bfloat16 hx = __float2bfloat16(v.x), hy = __float2bfloat16(v.y);
        __nv_bfloat16 hz = __float2bfloat16(v.z), hw = __float2bfloat16(v.w);
        __nv_bfloat16 lx = __float2bfloat16(v.x - __bfloat162float(hx));
        __nv_bfloat16 ly = __float2bfloat16(v.y - __bfloat162float(hy));
        __nv_bfloat16 lz = __float2bfloat16(v.z - __bfloat162float(hz));
        __nv_bfloat16 lw = __float2bfloat16(v.w - __bfloat162float(hw));
        int base = r * SASTR + 2 * c4;
        sAh[base]     = bfpack(hx, hy);
        sAh[base + 1] = bfpack(hz, hw);
        sAl[base]     = bfpack(lx, ly);
        sAl[base + 1] = bfpack(lz, lw);
    }
    __syncthreads();

    const int warp = tid >> 5, lane = tid & 31;
    const int tq = lane >> 2;
    const int tr = lane & 3;
    const int wcol = warp * 16;
    const int wtile2 = warp * 2;

    float acc[4][2][4];
#pragma unroll
    for (int mi = 0; mi < 4; mi++)
#pragma unroll
        for (int ni = 0; ni < 2; ni++)
#pragma unroll
            for (int v = 0; v < 4; v++) acc[mi][ni][v] = 0.f;

    // ---- GEMM1 ----
    mma_gemm_pass(g_Wbh, g_Wbl, sAh, sAl, acc, tq, tr, wtile2, lane);
    __syncthreads();   // all warps done reading sA before epilogue overwrites it

    // epilogue 1: relu(acc + b1) -> sAh/sAl (packed bf16 pairs, col pair = word)
    {
        float bias[2][2];
#pragma unroll
        for (int ni = 0; ni < 2; ni++) {
            bias[ni][0] = __ldg(b1 + wcol + ni * 8 + 2 * tr);
            bias[ni][1] = __ldg(b1 + wcol + ni * 8 + 2 * tr + 1);
        }
#pragma unroll
        for (int mi = 0; mi < 4; mi++) {
#pragma unroll
            for (int ni = 0; ni < 2; ni++) {
                int wd = warp * 8 + ni * 4 + tr;   // word index of col pair
                int ra = mi * 16 + tq, rb = ra + 8;
                float v0 = fmaxf(acc[mi][ni][0] + bias[ni][0], 0.f);
                float v1 = fmaxf(acc[mi][ni][1] + bias[ni][1], 0.f);
                float v2 = fmaxf(acc[mi][ni][2] + bias[ni][0], 0.f);
                float v3 = fmaxf(acc[mi][ni][3] + bias[ni][1], 0.f);
                __nv_bfloat16 h0 = __float2bfloat16(v0), h1 = __float2bfloat16(v1);
                __nv_bfloat16 h2 = __float2bfloat16(v2), h3 = __float2bfloat16(v3);
                sAh[ra * SASTR + wd] = bfpack(h0, h1);
                sAh[rb * SASTR + wd] = bfpack(h2, h3);
                sAl[ra * SASTR + wd] = bfpack(
                    __float2bfloat16(v0 - __bfloat162float(h0)),
                    __float2bfloat16(v1 - __bfloat162float(h1)));
                sAl[rb * SASTR + wd] = bfpack(
                    __float2bfloat16(v2 - __bfloat162float(h2)),
                    __float2bfloat16(v3 - __bfloat162float(h3)));
                acc[mi][ni][0] = 0.f; acc[mi][ni][1] = 0.f;
                acc[mi][ni][2] = 0.f; acc[mi][ni][3] = 0.f;
            }
        }
    }
    __syncthreads();   // epilogue writes visible before GEMM2 reads sA

    // ---- GEMM2 ----
    mma_gemm_pass(g_Wbh + 8192, g_Wbl + 8192, sAh, sAl, acc, tq, tr, wtile2, lane);

    // epilogue 2: acc + b2 -> g_xres (fp32)
    {
        float bias[2][2];
#pragma unroll
        for (int ni = 0; ni < 2; ni++) {
            bias[ni][0] = __ldg(b2 + wcol + ni * 8 + 2 * tr);
            bias[ni][1] = __ldg(b2 + wcol + ni * 8 + 2 * tr + 1);
        }
#pragma unroll
        for (int mi = 0; mi < 4; mi++) {
#pragma unroll
            for (int ni = 0; ni < 2; ni++) {
                int col = wcol + ni * 8 + 2 * tr;
                int r = row0 + mi * 16 + tq;
                if (r < NN) {
                    float2 v;
                    v.x = acc[mi][ni][0] + bias[ni][0];
                    v.y = acc[mi][ni][1] + bias[ni][1];
                    *(float2*)(g_xres + (size_t)r * DD + col) = v;
                }
                if (r + 8 < NN) {
                    float2 v;
                    v.x = acc[mi][ni][2] + bias[ni][0];
                    v.y = acc[mi][ni][3] + bias[ni][1];
                    *(float2*)(g_xres + (size_t)(r + 8) * DD + col) = v;
                }
            }
        }
    }
}

// ---------------------------------------------------------------------------
// Kernel 3: pocket pooling, atomic-free. Block = (graph b, slice s).
// ---------------------------------------------------------------------------
__global__ void pool_kernel(const float* __restrict__ mask) {
    __shared__ float sacc[8][KK * DD];
    __shared__ float scnt[8][KK];
    const int b = blockIdx.x / PS;
    const int s = blockIdx.x % PS;
    const int gs = g_gstart[b];
    const int len = g_gstart[b + 1] - gs;
    const int start = gs + (len * s) / PS;
    const int end = gs + (len * (s + 1)) / PS;

    const int wib = threadIdx.x >> 5;
    const int lane = threadIdx.x & 31;
    float* acc = sacc[wib];
    for (int i = lane; i < KK * DD; i += 32) acc[i] = 0.f;
    float cnt = 0.f;

    for (int n = start + wib; n < end; n += 8) {
        float m = (lane < KK) ? mask[(size_t)n * KK + lane] : 0.f;
        float4 xv = *(const float4*)(g_xres + (size_t)n * DD + lane * 4);
#pragma unroll
        for (int k = 0; k < KK; k++) {
            float mk = __shfl_sync(0xffffffffu, m, k);
            if (mk != 0.f) {
                float4* a = (float4*)(acc + k * DD + lane * 4);
                float4 v = *a;
                v.x += xv.x; v.y += xv.y; v.z += xv.z; v.w += xv.w;
                *a = v;
            }
        }
        cnt += m;
    }
    if (lane < KK) scnt[wib][lane] = cnt;
    __syncthreads();

    float* outp = g_part + (size_t)blockIdx.x * KK * DD;
    for (int i = threadIdx.x; i < KK * DD; i += blockDim.x) {
        float v = 0.f;
#pragma unroll
        for (int w = 0; w < 8; w++) v += sacc[w][i];
        outp[i] = v;
    }
    if (threadIdx.x < KK) {
        float c = 0.f;
#pragma unroll
        for (int w = 0; w < 8; w++) c += scnt[w][threadIdx.x];
        g_cntpart[blockIdx.x * KK + threadIdx.x] = c;
    }
}

// ---------------------------------------------------------------------------
// Kernel 3b: reduce partials -> g_psum, g_pcnt
// ---------------------------------------------------------------------------
__global__ void reduce_kernel() {
    int tid = blockIdx.x * blockDim.x + threadIdx.x;
    int stride = gridDim.x * blockDim.x;
    for (int i = tid; i < BB * KK * DD; i += stride) {
        int b = i / (KK * DD);
        int j = i % (KK * DD);
        float v = 0.f;
#pragma unroll
        for (int s = 0; s < PS; s++) v += g_part[(size_t)(b * PS + s) * KK * DD + j];
        g_psum[i] = v;
    }
    for (int i = tid; i < BB * KK; i += stride) {
        int b = i / KK;
        int k = i % KK;
        float c = 0.f;
#pragma unroll
        for (int s = 0; s < PS; s++) c += g_cntpart[(b * PS + s) * KK + k];
        g_pcnt[i] = c;
    }
}

// ---------------------------------------------------------------------------
// Kernel 4: pocket_emb = (psum/(cnt+1e-9)) @ Wv + bv. Warp per row (512 rows).
// ---------------------------------------------------------------------------
__global__ void pemb_kernel(const float* __restrict__ Wv, const float* __restrict__ bv) {
    const int lane = threadIdx.x & 31;
    const int r = blockIdx.x * (blockDim.x >> 5) + (threadIdx.x >> 5);
    if (r >= BB * KK) return;
    const float rinv = 1.f / (g_pcnt[r] + 1e-9f);
    const int c0 = lane * 4;
    float4 acc = *(const float4*)(bv + c0);
#pragma unroll 8
    for (int d = 0; d < DD; d++) {
        float a = g_psum[r * DD + d] * rinv;
        float4 w = __ldg((const float4*)(Wv + d * DD + c0));
        acc.x += a * w.x; acc.y += a * w.y; acc.z += a * w.z; acc.w += a * w.w;
    }
    *(float4*)(g_pemb + r * DD + c0) = acc;
}

// ---------------------------------------------------------------------------
// Kernel 5: residual pocket feedback + LayerNorm + ReLU. Warp per node.
// ---------------------------------------------------------------------------
__global__ void final_kernel(const float* __restrict__ mask, const int* __restrict__ batch,
                             const float* __restrict__ gamma, const float* __restrict__ beta,
                             float* __restrict__ out) {
    const int lane = threadIdx.x & 31;
    const int gw = blockIdx.x * (blockDim.x >> 5) + (threadIdx.x >> 5);
    const int tw = gridDim.x * (blockDim.x >> 5);
    const int c0 = lane * 4;
    const float4 gm = *(const float4*)(gamma + c0);
    const float4 bt = *(const float4*)(beta + c0);

    for (int n = gw; n < NN; n += tw) {
        int g = batch[n];
        float m = (lane < KK) ? mask[(size_t)n * KK + lane] : 0.f;
        float4 v = *(const float4*)(g_xres + (size_t)n * DD + c0);
        const float* pe = g_pemb + (size_t)g * KK * DD;
#pragma unroll
        for (int k = 0; k < KK; k++) {
            float mk = __shfl_sync(0xffffffffu, m, k);
            if (mk != 0.f) {
                float4 p = __ldg((const float4*)(pe + k * DD + c0));
                v.x += p.x; v.y += p.y; v.z += p.z; v.w += p.w;
            }
        }
        float s = v.x + v.y + v.z + v.w;
#pragma unroll
        for (int off = 16; off; off >>= 1) s += __shfl_xor_sync(0xffffffffu, s, off);
        float mu = s * (1.f / 128.f);
        float dx = v.x - mu, dy = v.y - mu, dz = v.z - mu, dw = v.w - mu;
        float sq = dx * dx + dy * dy + dz * dz + dw * dw;
#pragma unroll
        for (int off = 16; off; off >>= 1) sq += __shfl_xor_sync(0xffffffffu, sq, off);
        float rstd = rsqrtf(sq * (1.f / 128.f) + 1e-5f);
        float4 y;
        y.x = fmaxf(dx * rstd * gm.x + bt.x, 0.f);
        y.y = fmaxf(dy * rstd * gm.y + bt.y, 0.f);
        y.z = fmaxf(dz * rstd * gm.z + bt.z, 0.f);
        y.w = fmaxf(dw * rstd * gm.w + bt.w, 0.f);
        *(float4*)(out + (size_t)n * DD + c0) = y;
    }
}

// ---------------------------------------------------------------------------
extern "C" void kernel_launch(void* const* d_in, const int* in_sizes, int n_in,
                              void* d_out, int out_size) {
    const float* x     = (const float*)d_in[0];
    const int*   ei    = (const int*)d_in[1];
    const float* ea    = (const float*)d_in[2];
    const float* pmask = (const float*)d_in[3];
    const int*   batch = (const int*)d_in[4];
    const float* We    = (const float*)d_in[5];
    const float* be    = (const float*)d_in[6];
    const float* W1    = (const float*)d_in[7];
    const float* b1    = (const float*)d_in[8];
    const float* W2    = (const float*)d_in[9];
    const float* b2    = (const float*)d_in[10];
    const float* eps   = (const float*)d_in[11];
    const float* gamma = (const float*)d_in[12];
    const float* beta  = (const float*)d_in[13];
    const float* Wv    = (const float*)d_in[14];
    const float* bv    = (const float*)d_in[15];
    float* out = (float*)d_out;

    const int MLP_SMEM = 2 * 64 * SASTR * 4;   // 34816 bytes (sAh + sAl)
    cudaFuncSetAttribute(mlp_fused_kernel, cudaFuncAttributeMaxDynamicSharedMemorySize, MLP_SMEM);

    init_kernel<<<2048, 256>>>(x, eps);
    bounds_kernel<<<(NN + 255) / 256, 256>>>(batch);
    wconv_kernel<<<32, 256>>>(W1, W2);
    edge_kernel<<<4096, 256>>>(x, ei, ea, We, be);
    mlp_fused_kernel<<<(NN + 63) / 64, 256, MLP_SMEM>>>(b1, b2);
    pool_kernel<<<BB * PS, 256>>>(pmask);
    reduce_kernel<<<64, 256>>>();
    pemb_kernel<<<(BB * KK + 7) / 8, 256>>>(Wv, bv);
    final_kernel<<<2048, 256>>>(pmask, batch, gamma, beta, out);
}